// round 3
// baseline (speedup 1.0000x reference)
#include <cuda_runtime.h>
#include <cuda_bf16.h>
#include <math.h>
#include <stdint.h>

// ---------------- problem constants ----------------
#define NMAX    100000
#define NNZMAX  1600000
#define D0      128

typedef unsigned long long ull;

// ---------------- device scratch (no cudaMalloc allowed) ----------------
__device__ int   g_cnt[NMAX];
__device__ int   g_off[NMAX + 1];
__device__ int   g_col[NNZMAX];
__device__ float g_val[NNZMAX];
__device__ float g_side[(size_t)NMAX * 128];
__device__ float g_e1[(size_t)NMAX * 128];
__device__ float g_e2[(size_t)NMAX * 64];
__device__ float g_e3[(size_t)NMAX * 32];

// ---------------- f32x2 packed math helpers ----------------
__device__ __forceinline__ ull pack2(float x, float y) {
    ull r;
    asm("mov.b64 %0, {%1, %2};" : "=l"(r) : "f"(x), "f"(y));
    return r;
}
__device__ __forceinline__ void unpack2(ull v, float& x, float& y) {
    asm("mov.b64 {%0, %1}, %2;" : "=f"(x), "=f"(y) : "l"(v));
}
__device__ __forceinline__ void fma2(ull& d, ull a, ull b) {
    asm("fma.rn.f32x2 %0, %1, %2, %0;" : "+l"(d) : "l"(a), "l"(b));
}

__device__ __forceinline__ float lrelu(float x) {
    return fmaxf(x, 0.01f * x);  // leaky_relu, slope 0.01 (jax default)
}

// ---------------- CSR build ----------------
__global__ void k_zero(float* out, int n) {
    int i = blockIdx.x * blockDim.x + threadIdx.x;
    if (i < n) g_cnt[i] = 0;
    if (i == 0) out[0] = 0.f;
}

__global__ void k_hist(const int* __restrict__ er, int nnz) {
    int i = blockIdx.x * blockDim.x + threadIdx.x;
    if (i < nnz) atomicAdd(&g_cnt[er[i]], 1);
}

// single-block exclusive scan of g_cnt -> g_off, zeroing g_cnt for reuse as cursor
__global__ void k_scan(int n, int nnz) {
    __shared__ int warp_sums[32];
    __shared__ int s_carry;
    int tid = threadIdx.x, lane = tid & 31, wid = tid >> 5;
    if (tid == 0) s_carry = 0;
    __syncthreads();
    for (int base = 0; base < n; base += 1024) {
        int i = base + tid;
        int v = (i < n) ? g_cnt[i] : 0;
        if (i < n) g_cnt[i] = 0;
        int x = v;
#pragma unroll
        for (int d = 1; d < 32; d <<= 1) {
            int t = __shfl_up_sync(0xffffffffu, x, d);
            if (lane >= d) x += t;
        }
        if (lane == 31) warp_sums[wid] = x;
        __syncthreads();
        if (wid == 0) {
            int w = warp_sums[lane];
#pragma unroll
            for (int d = 1; d < 32; d <<= 1) {
                int t = __shfl_up_sync(0xffffffffu, w, d);
                if (lane >= d) w += t;
            }
            warp_sums[lane] = w;
        }
        __syncthreads();
        int warp_off = (wid == 0) ? 0 : warp_sums[wid - 1];
        if (i < n) g_off[i] = s_carry + warp_off + x - v;
        __syncthreads();  // everyone has read s_carry
        if (tid == 1023) s_carry += warp_sums[31];
        __syncthreads();
    }
    if (threadIdx.x == 0) g_off[n] = nnz;
}

__global__ void k_scatter(const int* __restrict__ er, const int* __restrict__ ec,
                          const float* __restrict__ ev, int nnz) {
    int i = blockIdx.x * blockDim.x + threadIdx.x;
    if (i >= nnz) return;
    int r = er[i];
    int pos = g_off[r] + atomicAdd(&g_cnt[r], 1);
    g_col[pos] = ec[i];
    g_val[pos] = ev[i];
}

// ---------------- SpMM: side[row] = sum_e val_e * ego[col_e]  (one warp/row) ----
template <int D>
__global__ void k_spmm(const float* __restrict__ ego, float* __restrict__ side, int n) {
    int row = blockIdx.x * (blockDim.x >> 5) + (threadIdx.x >> 5);
    if (row >= n) return;
    int lane = threadIdx.x & 31;
    int s = g_off[row], e = g_off[row + 1];
    if (D == 128) {
        float4 acc = make_float4(0.f, 0.f, 0.f, 0.f);
        const float4* egp = (const float4*)ego;
        for (int i = s; i < e; i++) {
            int   c = __ldg(&g_col[i]);
            float v = __ldg(&g_val[i]);
            float4 x = egp[(size_t)c * 32 + lane];
            acc.x = fmaf(v, x.x, acc.x);
            acc.y = fmaf(v, x.y, acc.y);
            acc.z = fmaf(v, x.z, acc.z);
            acc.w = fmaf(v, x.w, acc.w);
        }
        ((float4*)side)[(size_t)row * 32 + lane] = acc;
    } else {  // D == 64
        float2 acc = make_float2(0.f, 0.f);
        const float2* egp = (const float2*)ego;
        for (int i = s; i < e; i++) {
            int   c = __ldg(&g_col[i]);
            float v = __ldg(&g_val[i]);
            float2 x = egp[(size_t)c * 32 + lane];
            acc.x = fmaf(v, x.x, acc.x);
            acc.y = fmaf(v, x.y, acc.y);
        }
        ((float2*)side)[(size_t)row * 32 + lane] = acc;
    }
}

// -------- bi-interaction + dual GEMM:
// out = lrelu((ego+side)@W1 + b1) + lrelu((ego*side)@W2 + b2)
// 256 threads, 64-row tiles; packed f32x2 path for DOUT>=64.
template <int DIN, int DOUT>
__global__ void __launch_bounds__(256, 1)
k_bi(const float* __restrict__ ego, const float* __restrict__ side,
     const float* __restrict__ W1, const float* __restrict__ b1,
     const float* __restrict__ W2, const float* __restrict__ b2,
     float* __restrict__ out, int n) {
    extern __shared__ float sm[];
    int tid = threadIdx.x, lane = tid & 31, wid = tid >> 5;

    if constexpr (DOUT >= 64) {
        constexpr int PAIRS = DOUT / 2;
        constexpr int J = DOUT / 64;  // col-pairs per lane
        float2* Wp1 = (float2*)sm;                 // [DIN][PAIRS]
        float2* Wp2 = Wp1 + DIN * PAIRS;
        float2* AM  = Wp2 + DIN * PAIRS;           // [64][DIN] (a, m)

        for (int idx = tid; idx < DIN * PAIRS; idx += 256) {
            int k = idx / PAIRS, p = idx % PAIRS;
            Wp1[idx] = make_float2(W1[k * DOUT + p], W1[k * DOUT + p + PAIRS]);
            Wp2[idx] = make_float2(W2[k * DOUT + p], W2[k * DOUT + p + PAIRS]);
        }
        float2 bias1[J], bias2[J];
#pragma unroll
        for (int j = 0; j < J; j++) {
            int c0 = lane + 32 * j;
            bias1[j] = make_float2(b1[c0], b1[c0 + PAIRS]);
            bias2[j] = make_float2(b2[c0], b2[c0 + PAIRS]);
        }

        int ntiles = (n + 63) / 64;
        for (int t = blockIdx.x; t < ntiles; t += gridDim.x) {
            int row0 = t * 64;
            __syncthreads();  // AM reuse + (first iter) W visibility
            for (int idx = tid; idx < 64 * DIN; idx += 256) {
                int r = idx / DIN, k = idx % DIN;
                int row = row0 + r;
                float eg = 0.f, sd = 0.f;
                if (row < n) {
                    eg = ego[(size_t)row * DIN + k];
                    sd = side[(size_t)row * DIN + k];
                }
                AM[idx] = make_float2(eg + sd, eg * sd);
            }
            __syncthreads();

            ull acc1[8][J], acc2[8][J];
#pragma unroll
            for (int r = 0; r < 8; r++)
#pragma unroll
                for (int j = 0; j < J; j++) { acc1[r][j] = 0ull; acc2[r][j] = 0ull; }

#pragma unroll 2
            for (int k = 0; k < DIN; k++) {
                ull w1[J], w2[J];
#pragma unroll
                for (int j = 0; j < J; j++) {
                    w1[j] = *(const ull*)&Wp1[k * PAIRS + lane + 32 * j];
                    w2[j] = *(const ull*)&Wp2[k * PAIRS + lane + 32 * j];
                }
#pragma unroll
                for (int r = 0; r < 8; r++) {
                    float2 am = AM[(wid * 8 + r) * DIN + k];  // broadcast
                    ull aa = pack2(am.x, am.x);
                    ull mm = pack2(am.y, am.y);
#pragma unroll
                    for (int j = 0; j < J; j++) {
                        fma2(acc1[r][j], aa, w1[j]);
                        fma2(acc2[r][j], mm, w2[j]);
                    }
                }
            }
#pragma unroll
            for (int r = 0; r < 8; r++) {
                int row = row0 + wid * 8 + r;
                if (row >= n) continue;
#pragma unroll
                for (int j = 0; j < J; j++) {
                    float a1x, a1y, a2x, a2y;
                    unpack2(acc1[r][j], a1x, a1y);
                    unpack2(acc2[r][j], a2x, a2y);
                    int c0 = lane + 32 * j;
                    out[(size_t)row * DOUT + c0] =
                        lrelu(a1x + bias1[j].x) + lrelu(a2x + bias2[j].x);
                    out[(size_t)row * DOUT + c0 + PAIRS] =
                        lrelu(a1y + bias1[j].y) + lrelu(a2y + bias2[j].y);
                }
            }
        }
    } else {  // DOUT == 32 plain path
        float*  W1s = sm;
        float*  W2s = sm + DIN * DOUT;
        float2* AM  = (float2*)(sm + 2 * DIN * DOUT);
        for (int idx = tid; idx < DIN * DOUT; idx += 256) {
            W1s[idx] = W1[idx];
            W2s[idx] = W2[idx];
        }
        float bb1 = b1[lane], bb2 = b2[lane];
        int ntiles = (n + 63) / 64;
        for (int t = blockIdx.x; t < ntiles; t += gridDim.x) {
            int row0 = t * 64;
            __syncthreads();
            for (int idx = tid; idx < 64 * DIN; idx += 256) {
                int r = idx / DIN, k = idx % DIN;
                int row = row0 + r;
                float eg = 0.f, sd = 0.f;
                if (row < n) {
                    eg = ego[(size_t)row * DIN + k];
                    sd = side[(size_t)row * DIN + k];
                }
                AM[idx] = make_float2(eg + sd, eg * sd);
            }
            __syncthreads();
            float acc1[8] = {0.f}, acc2[8] = {0.f};
#pragma unroll 4
            for (int k = 0; k < DIN; k++) {
                float w1 = W1s[k * DOUT + lane];
                float w2 = W2s[k * DOUT + lane];
#pragma unroll
                for (int r = 0; r < 8; r++) {
                    float2 am = AM[(wid * 8 + r) * DIN + k];
                    acc1[r] = fmaf(am.x, w1, acc1[r]);
                    acc2[r] = fmaf(am.y, w2, acc2[r]);
                }
            }
#pragma unroll
            for (int r = 0; r < 8; r++) {
                int row = row0 + wid * 8 + r;
                if (row < n)
                    out[(size_t)row * DOUT + lane] =
                        lrelu(acc1[r] + bb1) + lrelu(acc2[r] + bb2);
            }
        }
    }
}

// ---------------- loss: warp per sample ----------------
#define WRED(x)                                                   \
    {                                                             \
        for (int _o = 16; _o > 0; _o >>= 1)                       \
            (x) += __shfl_xor_sync(0xffffffffu, (x), _o);         \
    }

__global__ void k_loss(const float* __restrict__ emb, const int* __restrict__ uid,
                       const int* __restrict__ pid, const int* __restrict__ nid,
                       float* __restrict__ out, int B, float invB) {
    int s = blockIdx.x * (blockDim.x >> 5) + (threadIdx.x >> 5);
    if (s >= B) return;
    int lane = threadIdx.x & 31;
    int ru = uid[s], rp = pid[s], rn = nid[s];

    float q0u = 0, q0p = 0, q0n = 0, d0p = 0, d0n = 0;
    float q1u = 0, q1p = 0, q1n = 0, d1p = 0, d1n = 0;
    float q2u = 0, q2p = 0, q2n = 0, d2p = 0, d2n = 0;
    float q3u = 0, q3p = 0, q3n = 0, d3p = 0, d3n = 0;

#pragma unroll
    for (int i = 0; i < 4; i++) {
        int c = lane + 32 * i;
        float xu = emb[(size_t)ru * 128 + c];
        float xp = emb[(size_t)rp * 128 + c];
        float xn = emb[(size_t)rn * 128 + c];
        q0u += xu * xu; q0p += xp * xp; q0n += xn * xn;
        d0p += xu * xp; d0n += xu * xn;
    }
#pragma unroll
    for (int i = 0; i < 4; i++) {
        int c = lane + 32 * i;
        float xu = g_e1[(size_t)ru * 128 + c];
        float xp = g_e1[(size_t)rp * 128 + c];
        float xn = g_e1[(size_t)rn * 128 + c];
        q1u += xu * xu; q1p += xp * xp; q1n += xn * xn;
        d1p += xu * xp; d1n += xu * xn;
    }
#pragma unroll
    for (int i = 0; i < 2; i++) {
        int c = lane + 32 * i;
        float xu = g_e2[(size_t)ru * 64 + c];
        float xp = g_e2[(size_t)rp * 64 + c];
        float xn = g_e2[(size_t)rn * 64 + c];
        q2u += xu * xu; q2p += xp * xp; q2n += xn * xn;
        d2p += xu * xp; d2n += xu * xn;
    }
    {
        float xu = g_e3[(size_t)ru * 32 + lane];
        float xp = g_e3[(size_t)rp * 32 + lane];
        float xn = g_e3[(size_t)rn * 32 + lane];
        q3u += xu * xu; q3p += xp * xp; q3n += xn * xn;
        d3p += xu * xp; d3n += xu * xn;
    }

    WRED(q0u); WRED(q0p); WRED(q0n); WRED(d0p); WRED(d0n);
    WRED(q1u); WRED(q1p); WRED(q1n); WRED(d1p); WRED(d1n);
    WRED(q2u); WRED(q2p); WRED(q2n); WRED(d2p); WRED(d2n);
    WRED(q3u); WRED(q3p); WRED(q3n); WRED(d3p); WRED(d3n);

    if (lane == 0) {
        const float eps = 1e-12f;
        float i1u = 1.f / fmaxf(sqrtf(q1u), eps);
        float i1p = 1.f / fmaxf(sqrtf(q1p), eps);
        float i1n = 1.f / fmaxf(sqrtf(q1n), eps);
        float i2u = 1.f / fmaxf(sqrtf(q2u), eps);
        float i2p = 1.f / fmaxf(sqrtf(q2p), eps);
        float i2n = 1.f / fmaxf(sqrtf(q2n), eps);
        float i3u = 1.f / fmaxf(sqrtf(q3u), eps);
        float i3p = 1.f / fmaxf(sqrtf(q3p), eps);
        float i3n = 1.f / fmaxf(sqrtf(q3n), eps);

        float pos = d0p + d1p * i1u * i1p + d2p * i2u * i2p + d3p * i3u * i3p;
        float neg = d0n + d1n * i1u * i1n + d2n * i2u * i2n + d3n * i3u * i3n;

        float l2 = q0u + q0p + q0n
                 + q1u * i1u * i1u + q1p * i1p * i1p + q1n * i1n * i1n
                 + q2u * i2u * i2u + q2p * i2p * i2p + q2n * i2n * i2n
                 + q3u * i3u * i3u + q3p * i3p * i3p + q3n * i3n * i3n;

        float x = pos - neg;  // -log(sigmoid(x)) = softplus(-x)
        float cf = fmaxf(-x, 0.f) + log1pf(expf(-fabsf(x)));
        float contrib = (cf + 1e-5f * 0.5f * l2) * invB;
        atomicAdd(out, contrib);
    }
}

// ---------------- host ----------------
extern "C" void kernel_launch(void* const* d_in, const int* in_sizes, int n_in,
                              void* d_out, int out_size) {
    const float* emb  = (const float*)d_in[0];
    const float* W1_0 = (const float*)d_in[1];
    const float* b1_0 = (const float*)d_in[2];
    const float* W2_0 = (const float*)d_in[3];
    const float* b2_0 = (const float*)d_in[4];
    const float* W1_1 = (const float*)d_in[5];
    const float* b1_1 = (const float*)d_in[6];
    const float* W2_1 = (const float*)d_in[7];
    const float* b2_1 = (const float*)d_in[8];
    const float* W1_2 = (const float*)d_in[9];
    const float* b1_2 = (const float*)d_in[10];
    const float* W2_2 = (const float*)d_in[11];
    const float* b2_2 = (const float*)d_in[12];
    const int*   erow = (const int*)d_in[13];
    const int*   ecol = (const int*)d_in[14];
    const float* eval = (const float*)d_in[15];
    const int*   uid  = (const int*)d_in[16];
    const int*   pid  = (const int*)d_in[17];
    const int*   nid  = (const int*)d_in[18];

    int n   = in_sizes[0] / D0;
    int nnz = in_sizes[13];
    int B   = in_sizes[16];
    float* out = (float*)d_out;

    void* p;
    cudaGetSymbolAddress(&p, g_side); float* side = (float*)p;
    cudaGetSymbolAddress(&p, g_e1);   float* e1   = (float*)p;
    cudaGetSymbolAddress(&p, g_e2);   float* e2   = (float*)p;
    cudaGetSymbolAddress(&p, g_e3);   float* e3   = (float*)p;

    // dynamic smem sizes
    const int smem1 = (2 * 128 * 64 + 64 * 128) * 8;  // 196608
    const int smem2 = (2 * 128 * 32 + 64 * 128) * 8;  // 131072
    const int smem3 = 2 * 64 * 32 * 4 + 64 * 64 * 8;  // 49152
    cudaFuncSetAttribute((const void*)k_bi<128, 128>,
                         cudaFuncAttributeMaxDynamicSharedMemorySize, smem1);
    cudaFuncSetAttribute((const void*)k_bi<128, 64>,
                         cudaFuncAttributeMaxDynamicSharedMemorySize, smem2);
    cudaFuncSetAttribute((const void*)k_bi<64, 32>,
                         cudaFuncAttributeMaxDynamicSharedMemorySize, smem3);

    // CSR build
    k_zero<<<(n + 255) / 256, 256>>>(out, n);
    k_hist<<<(nnz + 255) / 256, 256>>>(erow, nnz);
    k_scan<<<1, 1024>>>(n, nnz);
    k_scatter<<<(nnz + 255) / 256, 256>>>(erow, ecol, eval, nnz);

    int spmm_grid = (n + 7) / 8;

    // layer 0: 128 -> 128
    k_spmm<128><<<spmm_grid, 256>>>(emb, side, n);
    k_bi<128, 128><<<148, 256, smem1>>>(emb, side, W1_0, b1_0, W2_0, b2_0, e1, n);

    // layer 1: 128 -> 64
    k_spmm<128><<<spmm_grid, 256>>>(e1, side, n);
    k_bi<128, 64><<<148, 256, smem2>>>(e1, side, W1_1, b1_1, W2_1, b2_1, e2, n);

    // layer 2: 64 -> 32
    k_spmm<64><<<spmm_grid, 256>>>(e2, side, n);
    k_bi<64, 32><<<592, 256, smem3>>>(e2, side, W1_2, b1_2, W2_2, b2_2, e3, n);

    // loss
    k_loss<<<(B + 7) / 8, 256>>>(emb, uid, pid, nid, out, B, 1.0f / (float)B);
}

// round 4
// speedup vs baseline: 1.9057x; 1.9057x over previous
#include <cuda_runtime.h>
#include <cuda_bf16.h>
#include <math.h>
#include <stdint.h>

// ---------------- problem constants ----------------
#define NMAX    100000
#define NNZMAX  1600000
#define D0      128

typedef unsigned int uint;

// ---------------- device scratch (no cudaMalloc allowed) ----------------
__device__ int   g_cnt[NMAX];
__device__ int   g_off[NMAX + 2];
__device__ int   g_bsum[128];
__device__ int2  g_cv[NNZMAX];          // packed {col, val_bits}
__device__ float g_side[(size_t)NMAX * 128];
__device__ float g_e1[(size_t)NMAX * 128];
__device__ float g_e2[(size_t)NMAX * 64];
__device__ float g_e3[(size_t)NMAX * 32];

// tf32-converted weights: W1_0(16384) W2_0(16384) W1_1(8192) W2_1(8192) W1_2(2048) W2_2(2048)
#define WT_TOTAL 53248
__device__ uint g_wt[WT_TOTAL];

// ---------------- helpers ----------------
__device__ __forceinline__ float lrelu(float x) {
    return fmaxf(x, 0.01f * x);  // leaky_relu slope 0.01 (jax default)
}
__device__ __forceinline__ uint to_tf32(float x) {
    uint r;
    asm("cvt.rna.tf32.f32 %0, %1;" : "=r"(r) : "f"(x));
    return r;
}
__device__ __forceinline__ void mma_tf32(float* d, uint a0, uint a1, uint a2, uint a3,
                                         uint b0, uint b1) {
    asm volatile(
        "mma.sync.aligned.m16n8k8.row.col.f32.tf32.tf32.f32 "
        "{%0,%1,%2,%3},{%4,%5,%6,%7},{%8,%9},{%0,%1,%2,%3};"
        : "+f"(d[0]), "+f"(d[1]), "+f"(d[2]), "+f"(d[3])
        : "r"(a0), "r"(a1), "r"(a2), "r"(a3), "r"(b0), "r"(b1));
}

// ---------------- weight conversion (fp32 -> tf32 bits), once per launch ----
__global__ void k_cvtW(const float* __restrict__ w10, const float* __restrict__ w20,
                       const float* __restrict__ w11, const float* __restrict__ w21,
                       const float* __restrict__ w12, const float* __restrict__ w22) {
    int i = blockIdx.x * blockDim.x + threadIdx.x;
    if (i >= WT_TOTAL) return;
    float v;
    if (i < 16384)       v = w10[i];
    else if (i < 32768)  v = w20[i - 16384];
    else if (i < 40960)  v = w11[i - 32768];
    else if (i < 49152)  v = w21[i - 40960];
    else if (i < 51200)  v = w12[i - 49152];
    else                 v = w22[i - 51200];
    g_wt[i] = to_tf32(v);
}

// ---------------- CSR build ----------------
__global__ void k_zero(float* out, int n) {
    int i = blockIdx.x * blockDim.x + threadIdx.x;
    if (i < n) g_cnt[i] = 0;
    if (i == 0) out[0] = 0.f;
}

__global__ void k_hist(const int* __restrict__ er, int nnz) {
    int i = blockIdx.x * blockDim.x + threadIdx.x;
    if (i < nnz) atomicAdd(&g_cnt[er[i]], 1);
}

// block-local exclusive scan over 1024 elems; writes partials + block totals
__global__ void k_scan1(int n) {
    __shared__ int warp_sums[32];
    int tid = threadIdx.x, lane = tid & 31, wid = tid >> 5;
    int i = blockIdx.x * 1024 + tid;
    int v = (i < n) ? g_cnt[i] : 0;
    if (i < n) g_cnt[i] = 0;  // reused as scatter cursor
    int x = v;
#pragma unroll
    for (int d = 1; d < 32; d <<= 1) {
        int t = __shfl_up_sync(0xffffffffu, x, d);
        if (lane >= d) x += t;
    }
    if (lane == 31) warp_sums[wid] = x;
    __syncthreads();
    if (wid == 0) {
        int w = warp_sums[lane];
#pragma unroll
        for (int d = 1; d < 32; d <<= 1) {
            int t = __shfl_up_sync(0xffffffffu, w, d);
            if (lane >= d) w += t;
        }
        warp_sums[lane] = w;
    }
    __syncthreads();
    int warp_off = (wid == 0) ? 0 : warp_sums[wid - 1];
    if (i <= n) g_off[i] = warp_off + x - v;  // partial exclusive (no block base)
    if (tid == 1023) g_bsum[blockIdx.x] = warp_sums[31];
}

// exclusive scan of block totals (G <= 128), in place
__global__ void k_scan2(int G) {
    __shared__ int ws[4];
    int tid = threadIdx.x, lane = tid & 31, w = tid >> 5;
    int v = (tid < G) ? g_bsum[tid] : 0;
    int x = v;
#pragma unroll
    for (int d = 1; d < 32; d <<= 1) {
        int t = __shfl_up_sync(0xffffffffu, x, d);
        if (lane >= d) x += t;
    }
    if (lane == 31) ws[w] = x;
    __syncthreads();
    int base = 0;
#pragma unroll
    for (int j = 0; j < 4; j++)
        if (j < w) base += ws[j];
    if (tid < 128) g_bsum[tid] = base + x - v;
}

__global__ void k_scatter(const int* __restrict__ er, const int* __restrict__ ec,
                          const float* __restrict__ ev, int nnz) {
    int i = blockIdx.x * blockDim.x + threadIdx.x;
    if (i >= nnz) return;
    int r = er[i];
    int pos = g_off[r] + g_bsum[r >> 10] + atomicAdd(&g_cnt[r], 1);
    g_cv[pos] = make_int2(ec[i], __float_as_int(ev[i]));
}

// ---------------- SpMM: side[row] = sum_e val_e * ego[col_e]  (one warp/row) ----
template <int D>
__global__ void k_spmm(const float* __restrict__ ego, float* __restrict__ side, int n) {
    int row = blockIdx.x * (blockDim.x >> 5) + (threadIdx.x >> 5);
    if (row >= n) return;
    int lane = threadIdx.x & 31;
    int s = g_off[row] + g_bsum[row >> 10];
    int e = g_off[row + 1] + g_bsum[(row + 1) >> 10];
    if (D == 128) {
        float4 acc = make_float4(0.f, 0.f, 0.f, 0.f);
        const float4* egp = (const float4*)ego;
        int i = s;
        for (; i + 4 <= e; i += 4) {
            int2 cv0 = __ldg(&g_cv[i]);
            int2 cv1 = __ldg(&g_cv[i + 1]);
            int2 cv2 = __ldg(&g_cv[i + 2]);
            int2 cv3 = __ldg(&g_cv[i + 3]);
            float4 x0 = egp[(size_t)cv0.x * 32 + lane];
            float4 x1 = egp[(size_t)cv1.x * 32 + lane];
            float4 x2 = egp[(size_t)cv2.x * 32 + lane];
            float4 x3 = egp[(size_t)cv3.x * 32 + lane];
            float v0 = __int_as_float(cv0.y), v1 = __int_as_float(cv1.y);
            float v2 = __int_as_float(cv2.y), v3 = __int_as_float(cv3.y);
            acc.x = fmaf(v0, x0.x, acc.x); acc.y = fmaf(v0, x0.y, acc.y);
            acc.z = fmaf(v0, x0.z, acc.z); acc.w = fmaf(v0, x0.w, acc.w);
            acc.x = fmaf(v1, x1.x, acc.x); acc.y = fmaf(v1, x1.y, acc.y);
            acc.z = fmaf(v1, x1.z, acc.z); acc.w = fmaf(v1, x1.w, acc.w);
            acc.x = fmaf(v2, x2.x, acc.x); acc.y = fmaf(v2, x2.y, acc.y);
            acc.z = fmaf(v2, x2.z, acc.z); acc.w = fmaf(v2, x2.w, acc.w);
            acc.x = fmaf(v3, x3.x, acc.x); acc.y = fmaf(v3, x3.y, acc.y);
            acc.z = fmaf(v3, x3.z, acc.z); acc.w = fmaf(v3, x3.w, acc.w);
        }
        for (; i < e; i++) {
            int2 cv = __ldg(&g_cv[i]);
            float v = __int_as_float(cv.y);
            float4 x = egp[(size_t)cv.x * 32 + lane];
            acc.x = fmaf(v, x.x, acc.x); acc.y = fmaf(v, x.y, acc.y);
            acc.z = fmaf(v, x.z, acc.z); acc.w = fmaf(v, x.w, acc.w);
        }
        ((float4*)side)[(size_t)row * 32 + lane] = acc;
    } else {  // D == 64
        float2 acc = make_float2(0.f, 0.f);
        const float2* egp = (const float2*)ego;
        int i = s;
        for (; i + 4 <= e; i += 4) {
            int2 cv0 = __ldg(&g_cv[i]);
            int2 cv1 = __ldg(&g_cv[i + 1]);
            int2 cv2 = __ldg(&g_cv[i + 2]);
            int2 cv3 = __ldg(&g_cv[i + 3]);
            float2 x0 = egp[(size_t)cv0.x * 32 + lane];
            float2 x1 = egp[(size_t)cv1.x * 32 + lane];
            float2 x2 = egp[(size_t)cv2.x * 32 + lane];
            float2 x3 = egp[(size_t)cv3.x * 32 + lane];
            float v0 = __int_as_float(cv0.y), v1 = __int_as_float(cv1.y);
            float v2 = __int_as_float(cv2.y), v3 = __int_as_float(cv3.y);
            acc.x = fmaf(v0, x0.x, acc.x); acc.y = fmaf(v0, x0.y, acc.y);
            acc.x = fmaf(v1, x1.x, acc.x); acc.y = fmaf(v1, x1.y, acc.y);
            acc.x = fmaf(v2, x2.x, acc.x); acc.y = fmaf(v2, x2.y, acc.y);
            acc.x = fmaf(v3, x3.x, acc.x); acc.y = fmaf(v3, x3.y, acc.y);
        }
        for (; i < e; i++) {
            int2 cv = __ldg(&g_cv[i]);
            float v = __int_as_float(cv.y);
            float2 x = egp[(size_t)cv.x * 32 + lane];
            acc.x = fmaf(v, x.x, acc.x); acc.y = fmaf(v, x.y, acc.y);
        }
        ((float2*)side)[(size_t)row * 32 + lane] = acc;
    }
}

// -------- bi-interaction dual GEMM on tensor cores (tf32 mma.sync):
// out = lrelu((ego+side)@W1 + b1) + lrelu((ego*side)@W2 + b2)
// CTA: 256 threads (8 warps = 2 M-warps x 4 N-warps), tile = 64 rows.
template <int DIN, int DOUT>
__global__ void __launch_bounds__(256)
k_bi(const float* __restrict__ ego, const float* __restrict__ side,
     const uint* __restrict__ W1t, const float* __restrict__ b1,
     const uint* __restrict__ W2t, const float* __restrict__ b2,
     float* __restrict__ out, int n) {
    constexpr int S      = DIN + 4;      // padded smem row stride (floats)
    constexpr int KSTEPS = DIN / 8;
    constexpr int NT     = DOUT / 32;    // n8-tiles per warp (4 warps along N)
    constexpr int MT     = 2;            // m16-tiles per warp (2 warps along M)

    extern __shared__ uint sm[];
    uint* As = sm;                  // [64][S] tf32 bits of (e+s)
    uint* Ms = sm + 64 * S;         // [64][S] tf32 bits of (e*s)

    int tid = threadIdx.x, lane = tid & 31;
    int wid = tid >> 5;
    int warp_n = wid & 3, warp_m = wid >> 2;
    int g = lane >> 2, t = lane & 3;
    int n0 = warp_n * (DOUT / 4);

    int row0 = blockIdx.x * 64;

    // stage A tiles (convert to tf32 once)
    for (int idx = tid; idx < 64 * (DIN / 4); idx += 256) {
        int r = idx / (DIN / 4);
        int kc = (idx % (DIN / 4)) * 4;
        int row = row0 + r;
        float4 e4 = make_float4(0.f, 0.f, 0.f, 0.f), s4 = e4;
        if (row < n) {
            e4 = *(const float4*)(ego + (size_t)row * DIN + kc);
            s4 = *(const float4*)(side + (size_t)row * DIN + kc);
        }
        uint4 a4, m4;
        a4.x = to_tf32(e4.x + s4.x); m4.x = to_tf32(e4.x * s4.x);
        a4.y = to_tf32(e4.y + s4.y); m4.y = to_tf32(e4.y * s4.y);
        a4.z = to_tf32(e4.z + s4.z); m4.z = to_tf32(e4.z * s4.z);
        a4.w = to_tf32(e4.w + s4.w); m4.w = to_tf32(e4.w * s4.w);
        *(uint4*)&As[r * S + kc] = a4;
        *(uint4*)&Ms[r * S + kc] = m4;
    }
    __syncthreads();

    float d1[MT][NT][4], d2[MT][NT][4];
#pragma unroll
    for (int mt = 0; mt < MT; mt++)
#pragma unroll
        for (int nt = 0; nt < NT; nt++)
#pragma unroll
            for (int q = 0; q < 4; q++) { d1[mt][nt][q] = 0.f; d2[mt][nt][q] = 0.f; }

#pragma unroll
    for (int ks = 0; ks < KSTEPS; ks++) {
        int k0 = ks * 8;
        uint b1f[NT][2], b2f[NT][2];
#pragma unroll
        for (int nt = 0; nt < NT; nt++) {
            int col = n0 + nt * 8 + g;
            b1f[nt][0] = __ldg(&W1t[(k0 + t) * DOUT + col]);
            b1f[nt][1] = __ldg(&W1t[(k0 + t + 4) * DOUT + col]);
            b2f[nt][0] = __ldg(&W2t[(k0 + t) * DOUT + col]);
            b2f[nt][1] = __ldg(&W2t[(k0 + t + 4) * DOUT + col]);
        }
#pragma unroll
        for (int mt = 0; mt < MT; mt++) {
            int rb = warp_m * 32 + mt * 16;
            uint a0 = As[(rb + g) * S + k0 + t];
            uint a1 = As[(rb + 8 + g) * S + k0 + t];
            uint a2 = As[(rb + g) * S + k0 + t + 4];
            uint a3 = As[(rb + 8 + g) * S + k0 + t + 4];
            uint m0 = Ms[(rb + g) * S + k0 + t];
            uint m1 = Ms[(rb + 8 + g) * S + k0 + t];
            uint m2 = Ms[(rb + g) * S + k0 + t + 4];
            uint m3 = Ms[(rb + 8 + g) * S + k0 + t + 4];
#pragma unroll
            for (int nt = 0; nt < NT; nt++) {
                mma_tf32(d1[mt][nt], a0, a1, a2, a3, b1f[nt][0], b1f[nt][1]);
                mma_tf32(d2[mt][nt], m0, m1, m2, m3, b2f[nt][0], b2f[nt][1]);
            }
        }
    }

    // epilogue: lrelu(d1+b1)+lrelu(d2+b2)
#pragma unroll
    for (int nt = 0; nt < NT; nt++) {
        int col = n0 + nt * 8 + t * 2;
        float bb1x = b1[col], bb1y = b1[col + 1];
        float bb2x = b2[col], bb2y = b2[col + 1];
#pragma unroll
        for (int mt = 0; mt < MT; mt++) {
            int r0 = row0 + warp_m * 32 + mt * 16 + g;
            if (r0 < n) {
                out[(size_t)r0 * DOUT + col] =
                    lrelu(d1[mt][nt][0] + bb1x) + lrelu(d2[mt][nt][0] + bb2x);
                out[(size_t)r0 * DOUT + col + 1] =
                    lrelu(d1[mt][nt][1] + bb1y) + lrelu(d2[mt][nt][1] + bb2y);
            }
            if (r0 + 8 < n) {
                out[(size_t)(r0 + 8) * DOUT + col] =
                    lrelu(d1[mt][nt][2] + bb1x) + lrelu(d2[mt][nt][2] + bb2x);
                out[(size_t)(r0 + 8) * DOUT + col + 1] =
                    lrelu(d1[mt][nt][3] + bb1y) + lrelu(d2[mt][nt][3] + bb2y);
            }
        }
    }
}

// ---------------- loss: warp per sample ----------------
#define WRED(x)                                                   \
    {                                                             \
        for (int _o = 16; _o > 0; _o >>= 1)                       \
            (x) += __shfl_xor_sync(0xffffffffu, (x), _o);         \
    }

__global__ void k_loss(const float* __restrict__ emb, const int* __restrict__ uid,
                       const int* __restrict__ pid, const int* __restrict__ nid,
                       float* __restrict__ out, int B, float invB) {
    int s = blockIdx.x * (blockDim.x >> 5) + (threadIdx.x >> 5);
    if (s >= B) return;
    int lane = threadIdx.x & 31;
    int ru = uid[s], rp = pid[s], rn = nid[s];

    float q0u = 0, q0p = 0, q0n = 0, d0p = 0, d0n = 0;
    float q1u = 0, q1p = 0, q1n = 0, d1p = 0, d1n = 0;
    float q2u = 0, q2p = 0, q2n = 0, d2p = 0, d2n = 0;
    float q3u = 0, q3p = 0, q3n = 0, d3p = 0, d3n = 0;

#pragma unroll
    for (int i = 0; i < 4; i++) {
        int c = lane + 32 * i;
        float xu = emb[(size_t)ru * 128 + c];
        float xp = emb[(size_t)rp * 128 + c];
        float xn = emb[(size_t)rn * 128 + c];
        q0u += xu * xu; q0p += xp * xp; q0n += xn * xn;
        d0p += xu * xp; d0n += xu * xn;
    }
#pragma unroll
    for (int i = 0; i < 4; i++) {
        int c = lane + 32 * i;
        float xu = g_e1[(size_t)ru * 128 + c];
        float xp = g_e1[(size_t)rp * 128 + c];
        float xn = g_e1[(size_t)rn * 128 + c];
        q1u += xu * xu; q1p += xp * xp; q1n += xn * xn;
        d1p += xu * xp; d1n += xu * xn;
    }
#pragma unroll
    for (int i = 0; i < 2; i++) {
        int c = lane + 32 * i;
        float xu = g_e2[(size_t)ru * 64 + c];
        float xp = g_e2[(size_t)rp * 64 + c];
        float xn = g_e2[(size_t)rn * 64 + c];
        q2u += xu * xu; q2p += xp * xp; q2n += xn * xn;
        d2p += xu * xp; d2n += xu * xn;
    }
    {
        float xu = g_e3[(size_t)ru * 32 + lane];
        float xp = g_e3[(size_t)rp * 32 + lane];
        float xn = g_e3[(size_t)rn * 32 + lane];
        q3u += xu * xu; q3p += xp * xp; q3n += xn * xn;
        d3p += xu * xp; d3n += xu * xn;
    }

    WRED(q0u); WRED(q0p); WRED(q0n); WRED(d0p); WRED(d0n);
    WRED(q1u); WRED(q1p); WRED(q1n); WRED(d1p); WRED(d1n);
    WRED(q2u); WRED(q2p); WRED(q2n); WRED(d2p); WRED(d2n);
    WRED(q3u); WRED(q3p); WRED(q3n); WRED(d3p); WRED(d3n);

    if (lane == 0) {
        const float eps = 1e-12f;
        float i1u = 1.f / fmaxf(sqrtf(q1u), eps);
        float i1p = 1.f / fmaxf(sqrtf(q1p), eps);
        float i1n = 1.f / fmaxf(sqrtf(q1n), eps);
        float i2u = 1.f / fmaxf(sqrtf(q2u), eps);
        float i2p = 1.f / fmaxf(sqrtf(q2p), eps);
        float i2n = 1.f / fmaxf(sqrtf(q2n), eps);
        float i3u = 1.f / fmaxf(sqrtf(q3u), eps);
        float i3p = 1.f / fmaxf(sqrtf(q3p), eps);
        float i3n = 1.f / fmaxf(sqrtf(q3n), eps);

        float pos = d0p + d1p * i1u * i1p + d2p * i2u * i2p + d3p * i3u * i3p;
        float neg = d0n + d1n * i1u * i1n + d2n * i2u * i2n + d3n * i3u * i3n;

        float l2 = q0u + q0p + q0n
                 + q1u * i1u * i1u + q1p * i1p * i1p + q1n * i1n * i1n
                 + q2u * i2u * i2u + q2p * i2p * i2p + q2n * i2n * i2n
                 + q3u * i3u * i3u + q3p * i3p * i3p + q3n * i3n * i3n;

        float x = pos - neg;  // -log(sigmoid(x)) = softplus(-x)
        float cf = fmaxf(-x, 0.f) + log1pf(expf(-fabsf(x)));
        float contrib = (cf + 1e-5f * 0.5f * l2) * invB;
        atomicAdd(out, contrib);
    }
}

// ---------------- host ----------------
extern "C" void kernel_launch(void* const* d_in, const int* in_sizes, int n_in,
                              void* d_out, int out_size) {
    const float* emb  = (const float*)d_in[0];
    const float* W1_0 = (const float*)d_in[1];
    const float* b1_0 = (const float*)d_in[2];
    const float* W2_0 = (const float*)d_in[3];
    const float* b2_0 = (const float*)d_in[4];
    const float* W1_1 = (const float*)d_in[5];
    const float* b1_1 = (const float*)d_in[6];
    const float* W2_1 = (const float*)d_in[7];
    const float* b2_1 = (const float*)d_in[8];
    const float* W1_2 = (const float*)d_in[9];
    const float* b1_2 = (const float*)d_in[10];
    const float* W2_2 = (const float*)d_in[11];
    const float* b2_2 = (const float*)d_in[12];
    const int*   erow = (const int*)d_in[13];
    const int*   ecol = (const int*)d_in[14];
    const float* eval = (const float*)d_in[15];
    const int*   uid  = (const int*)d_in[16];
    const int*   pid  = (const int*)d_in[17];
    const int*   nid  = (const int*)d_in[18];

    int n   = in_sizes[0] / D0;
    int nnz = in_sizes[13];
    int B   = in_sizes[16];
    float* out = (float*)d_out;

    void* p;
    cudaGetSymbolAddress(&p, g_side); float* side = (float*)p;
    cudaGetSymbolAddress(&p, g_e1);   float* e1   = (float*)p;
    cudaGetSymbolAddress(&p, g_e2);   float* e2   = (float*)p;
    cudaGetSymbolAddress(&p, g_e3);   float* e3   = (float*)p;
    cudaGetSymbolAddress(&p, g_wt);   const uint* wt = (const uint*)p;
    const uint* w1t0 = wt;
    const uint* w2t0 = wt + 16384;
    const uint* w1t1 = wt + 32768;
    const uint* w2t1 = wt + 40960;
    const uint* w1t2 = wt + 49152;
    const uint* w2t2 = wt + 51200;

    // dynamic smem: 2 tiles of [64][DIN+4] uints
    const int smemA = 2 * 64 * (128 + 4) * 4;  // 67584
    const int smemC = 2 * 64 * (64 + 4) * 4;   // 34816
    cudaFuncSetAttribute((const void*)k_bi<128, 128>,
                         cudaFuncAttributeMaxDynamicSharedMemorySize, smemA);
    cudaFuncSetAttribute((const void*)k_bi<128, 64>,
                         cudaFuncAttributeMaxDynamicSharedMemorySize, smemA);
    cudaFuncSetAttribute((const void*)k_bi<64, 32>,
                         cudaFuncAttributeMaxDynamicSharedMemorySize, smemC);

    // weight conversion + CSR build
    k_cvtW<<<(WT_TOTAL + 255) / 256, 256>>>(W1_0, W2_0, W1_1, W2_1, W1_2, W2_2);
    k_zero<<<(n + 255) / 256, 256>>>(out, n);
    k_hist<<<(nnz + 255) / 256, 256>>>(erow, nnz);
    int G = (n + 1 + 1023) / 1024;
    k_scan1<<<G, 1024>>>(n);
    k_scan2<<<1, 128>>>(G);
    k_scatter<<<(nnz + 255) / 256, 256>>>(erow, ecol, eval, nnz);

    int spmm_grid = (n + 7) / 8;
    int bi_grid   = (n + 63) / 64;

    // layer 0: 128 -> 128
    k_spmm<128><<<spmm_grid, 256>>>(emb, side, n);
    k_bi<128, 128><<<bi_grid, 256, smemA>>>(emb, side, w1t0, b1_0, w2t0, b2_0, e1, n);

    // layer 1: 128 -> 64
    k_spmm<128><<<spmm_grid, 256>>>(e1, side, n);
    k_bi<128, 64><<<bi_grid, 256, smemA>>>(e1, side, w1t1, b1_1, w2t1, b2_1, e2, n);

    // layer 2: 64 -> 32
    k_spmm<64><<<spmm_grid, 256>>>(e2, side, n);
    k_bi<64, 32><<<bi_grid, 256, smemC>>>(e2, side, w1t2, b1_2, w2t2, b2_2, e3, n);

    // loss
    k_loss<<<(B + 7) / 8, 256>>>(emb, uid, pid, nid, out, B, 1.0f / (float)B);
}